// round 13
// baseline (speedup 1.0000x reference)
#include <cuda_runtime.h>
#include <cuda_bf16.h>

// B=512, T=1024, IN=1, H=64
#define TLEN 1024
#define HDIM 64
#define GB   4              // batches per block (weights shared across all 4)
#define NTHR 128            // 64 units x 2 gate-pairs
#define NBLK 128            // 512 / GB -> one block per SM (128 <= 148)

typedef unsigned long long u64;

__device__ __forceinline__ u64 fma2(u64 a, u64 b, u64 c) {
    u64 d;
    asm("fma.rn.f32x2 %0, %1, %2, %3;" : "=l"(d) : "l"(a), "l"(b), "l"(c));
    return d;
}
__device__ __forceinline__ u64 add2(u64 a, u64 b) {
    u64 d;
    asm("add.rn.f32x2 %0, %1, %2;" : "=l"(d) : "l"(a), "l"(b));
    return d;
}
__device__ __forceinline__ u64 pack2(float lo, float hi) {
    u64 r;
    asm("mov.b64 %0, {%1, %2};" : "=l"(r) : "f"(lo), "f"(hi));
    return r;
}
__device__ __forceinline__ float lo_add_hi(u64 v) {
    float lo, hi;
    asm("mov.b64 {%0, %1}, %2;" : "=f"(lo), "=f"(hi) : "l"(v));
    return lo + hi;
}
__device__ __forceinline__ float ex2f(float x) {
    float r; asm("ex2.approx.f32 %0, %1;" : "=f"(r) : "f"(x)); return r;
}
__device__ __forceinline__ float rcpf(float x) {
    float r; asm("rcp.approx.f32 %0, %1;" : "=f"(r) : "f"(x)); return r;
}
// Gate rows PRE-SCALED by -log2(e) (sigmoid rows) or -2*log2(e) (tanh row):
//   sigmoid(a) = 1/(1+ex2(z));   tanh(a) = 2/(1+ex2(z)) - 1
#define NLOG2E  1.44269504f
#define N2LOG2E 2.88539008f

__global__ void __launch_bounds__(NTHR, 1) qlstm_kernel(
    const float* __restrict__ x,      // [512, 1024, 1]
    const float* __restrict__ W_ih,   // [256, 1]
    const float* __restrict__ W_hh,   // [256, 64]
    const float* __restrict__ b_ih,   // [256]
    const float* __restrict__ b_hh,   // [256]
    const float* __restrict__ W_lin,  // [1, 64]
    const float* __restrict__ b_lin,  // [1]
    float* __restrict__ out)          // [512]
{
    __shared__ __align__(16) float xs[GB][TLEN];       // 16 KB
    __shared__ __align__(16) float hsm[2][GB][HDIM];   // 2 KB, double-buffered

    const int tid = threadIdx.x;
    const int p   = tid & 1;      // 0 -> gates {i,f}; 1 -> gates {g,o}
    const int m   = tid >> 1;     // hidden unit 0..63
    const int bb  = blockIdx.x * GB;

    // ---- stage x (coalesced, one-time) ----
    for (int i = tid; i < GB * TLEN; i += NTHR)
        xs[i >> 10][i & (TLEN - 1)] = x[(bb + (i >> 10)) * TLEN + (i & (TLEN - 1))];

    // ---- 2 full-K W_hh rows -> regs, prescaled (128 regs) ----
    const int   r0   = p ? 128 + m : m;        // g-row  : i-row
    const int   r1   = p ? 192 + m : 64 + m;   // o-row  : f-row
    const float scl0 = p ? -N2LOG2E : -NLOG2E; // tanh row gets 2x scale
    const float scl1 = -NLOG2E;

    u64 w0[32], w1[32];
    {
        const float4* a = reinterpret_cast<const float4*>(W_hh + r0 * HDIM);
        const float4* b = reinterpret_cast<const float4*>(W_hh + r1 * HDIM);
        #pragma unroll
        for (int k = 0; k < 16; k++) {
            float4 v = a[k];
            w0[2 * k]     = pack2(scl0 * v.x, scl0 * v.y);
            w0[2 * k + 1] = pack2(scl0 * v.z, scl0 * v.w);
            float4 u = b[k];
            w1[2 * k]     = pack2(scl1 * u.x, scl1 * u.y);
            w1[2 * k + 1] = pack2(scl1 * u.z, scl1 * u.w);
        }
    }
    const float wih0 = scl0 * W_ih[r0], bia0 = scl0 * (b_ih[r0] + b_hh[r0]);
    const float wih1 = scl1 * W_ih[r1], bia1 = scl1 * (b_ih[r1] + b_hh[r1]);

    for (int i = tid; i < 2 * GB * HDIM; i += NTHR)
        reinterpret_cast<float*>(hsm)[i] = 0.0f;

    float c[GB] = {0.0f, 0.0f, 0.0f, 0.0f};   // live in p==0 lanes only
    __syncthreads();

    const unsigned FULL = 0xffffffffu;

    auto step = [&](int t, const float (*hin)[HDIM], float (*hout)[HDIM]) {
        // Sequential batch bodies: batch g's tail overlaps batch g+1's FMA
        // chain (independent streams, ptxas pipelines across iterations).
        #pragma unroll
        for (int g = 0; g < GB; g++) {
            // full h (64 floats) as 32 packed pairs; broadcast LDS.128
            const ulonglong2* hp = reinterpret_cast<const ulonglong2*>(hin[g]);
            u64 h2[32];
            #pragma unroll
            for (int k = 0; k < 16; k++) {
                ulonglong2 v = hp[k];
                h2[2 * k] = v.x; h2[2 * k + 1] = v.y;
            }
            const float xv = xs[g][t];
            // 2 rows x 2 split accumulators (depth 16 each)
            u64 aA0 = pack2(fmaf(xv, wih0, bia0), 0.0f), aB0 = 0ull;
            u64 aA1 = pack2(fmaf(xv, wih1, bia1), 0.0f), aB1 = 0ull;
            #pragma unroll
            for (int k = 0; k < 16; k++) {
                aA0 = fma2(w0[k],      h2[k],      aA0);
                aB0 = fma2(w0[16 + k], h2[16 + k], aB0);
                aA1 = fma2(w1[k],      h2[k],      aA1);
                aB1 = fma2(w1[16 + k], h2[16 + k], aB1);
            }
            const float z0 = lo_add_hi(add2(aA0, aB0));
            const float z1 = lo_add_hi(add2(aA1, aB1));

            const float a0 = rcpf(1.0f + ex2f(z0));  // p0: sig(i)  p1: (tanh(g)+1)/2
            const float a1 = rcpf(1.0f + ex2f(z1));  // p0: sig(f)  p1: sig(o)
            const float tg = fmaf(2.0f, a0, -1.0f);  // p1: tanh(g)

            // two INDEPENDENT shuffles: p0 receives tanh(g) and sig(o)
            const float gr = __shfl_xor_sync(FULL, p ? tg : a0, 1);
            const float ox = __shfl_xor_sync(FULL, a1, 1);

            // p0: c = sig(f)*c + sig(i)*tanh(g)   (p1 lanes: garbage, unread)
            c[g] = fmaf(a1, c[g], a0 * gr);
            const float tc = fmaf(2.0f, rcpf(1.0f + ex2f(-N2LOG2E * c[g])), -1.0f);
            if (p == 0) hout[g][m] = ox * tc;        // h = sig(o)*tanh(c)
        }
    };

    #pragma unroll 1
    for (int t = 0; t < TLEN; t += 2) {
        step(t,     hsm[0], hsm[1]);
        __syncthreads();
        step(t + 1, hsm[1], hsm[0]);
        __syncthreads();
    }
    // t=1023 (odd) wrote hsm[0] -> final h in hsm[0]

    // ---- epilogue: out[b] = h_final . W_lin + b_lin ----
    const int w = tid >> 5, lane = tid & 31;
    if (w < GB) {
        const float* hf = hsm[0][w];
        float v = fmaf(hf[lane], W_lin[lane], hf[lane + 32] * W_lin[lane + 32]);
        #pragma unroll
        for (int d = 16; d >= 1; d >>= 1)
            v += __shfl_xor_sync(FULL, v, d);
        if (lane == 0) out[bb + w] = v + b_lin[0];
    }
}

extern "C" void kernel_launch(void* const* d_in, const int* in_sizes, int n_in,
                              void* d_out, int out_size) {
    const float* x     = (const float*)d_in[0];
    const float* W_ih  = (const float*)d_in[1];
    const float* W_hh  = (const float*)d_in[2];
    const float* b_ih  = (const float*)d_in[3];
    const float* b_hh  = (const float*)d_in[4];
    const float* W_lin = (const float*)d_in[5];
    const float* b_lin = (const float*)d_in[6];
    float* out = (float*)d_out;

    qlstm_kernel<<<NBLK, NTHR>>>(x, W_ih, W_hh, b_ih, b_hh, W_lin, b_lin, out);
}

// round 14
// speedup vs baseline: 1.9862x; 1.9862x over previous
#include <cuda_runtime.h>
#include <cuda_bf16.h>

// B=512, T=1024, IN=1, H=64
#define TLEN 1024
#define HDIM 64
#define GB   2              // batches per block (weights shared across both)
#define NTHR 128            // 64 units x 2 gate-pairs
#define NBLK 256            // 512 / GB -> 2 co-resident blocks per SM

typedef unsigned long long u64;

__device__ __forceinline__ u64 fma2(u64 a, u64 b, u64 c) {
    u64 d;
    asm("fma.rn.f32x2 %0, %1, %2, %3;" : "=l"(d) : "l"(a), "l"(b), "l"(c));
    return d;
}
__device__ __forceinline__ u64 add2(u64 a, u64 b) {
    u64 d;
    asm("add.rn.f32x2 %0, %1, %2;" : "=l"(d) : "l"(a), "l"(b));
    return d;
}
__device__ __forceinline__ u64 pack2(float lo, float hi) {
    u64 r;
    asm("mov.b64 %0, {%1, %2};" : "=l"(r) : "f"(lo), "f"(hi));
    return r;
}
__device__ __forceinline__ float lo_add_hi(u64 v) {
    float lo, hi;
    asm("mov.b64 {%0, %1}, %2;" : "=f"(lo), "=f"(hi) : "l"(v));
    return lo + hi;
}
// Single-MUFU tanh (sm_75+). Max abs err ~1.4e-5 -- far inside 1e-3 budget.
__device__ __forceinline__ float tanhfa(float x) {
    float r; asm("tanh.approx.f32 %0, %1;" : "=f"(r) : "f"(x)); return r;
}
// sigmoid(a) = 0.5*tanh(a/2) + 0.5 ; the /2 is PRE-FOLDED into the weight rows.

__global__ void __launch_bounds__(NTHR, 2) qlstm_kernel(
    const float* __restrict__ x,      // [512, 1024, 1]
    const float* __restrict__ W_ih,   // [256, 1]
    const float* __restrict__ W_hh,   // [256, 64]
    const float* __restrict__ b_ih,   // [256]
    const float* __restrict__ b_hh,   // [256]
    const float* __restrict__ W_lin,  // [1, 64]
    const float* __restrict__ b_lin,  // [1]
    float* __restrict__ out)          // [512]
{
    __shared__ __align__(16) float xs[GB][TLEN];       // 8 KB
    __shared__ __align__(16) float hsm[2][GB][HDIM];   // 1 KB, double-buffered

    const int tid = threadIdx.x;
    const int p   = tid & 1;      // 0 -> gates {i,f}; 1 -> gates {g,o}
    const int m   = tid >> 1;     // hidden unit 0..63
    const int bb  = blockIdx.x * GB;

    // ---- stage x (coalesced, one-time) ----
    for (int i = tid; i < GB * TLEN; i += NTHR)
        xs[i >> 10][i & (TLEN - 1)] = x[(bb + (i >> 10)) * TLEN + (i & (TLEN - 1))];

    // ---- 2 full-K W_hh rows -> regs (128 regs) ----
    // sigmoid rows prescaled by 0.5 (sigma(a) = 0.5*tanh(a/2)+0.5); g-row by 1.
    const int   r0   = p ? 128 + m : m;        // g-row  : i-row
    const int   r1   = p ? 192 + m : 64 + m;   // o-row  : f-row
    const float scl0 = p ? 1.0f : 0.5f;
    const float scl1 = 0.5f;

    u64 w0[32], w1[32];
    {
        const float4* a = reinterpret_cast<const float4*>(W_hh + r0 * HDIM);
        const float4* b = reinterpret_cast<const float4*>(W_hh + r1 * HDIM);
        #pragma unroll
        for (int k = 0; k < 16; k++) {
            float4 v = a[k];
            w0[2 * k]     = pack2(scl0 * v.x, scl0 * v.y);
            w0[2 * k + 1] = pack2(scl0 * v.z, scl0 * v.w);
            float4 u = b[k];
            w1[2 * k]     = pack2(scl1 * u.x, scl1 * u.y);
            w1[2 * k + 1] = pack2(scl1 * u.z, scl1 * u.w);
        }
    }
    const float wih0 = scl0 * W_ih[r0], bia0 = scl0 * (b_ih[r0] + b_hh[r0]);
    const float wih1 = scl1 * W_ih[r1], bia1 = scl1 * (b_ih[r1] + b_hh[r1]);

    for (int i = tid; i < 2 * GB * HDIM; i += NTHR)
        reinterpret_cast<float*>(hsm)[i] = 0.0f;

    float c[GB] = {0.0f, 0.0f};   // live in p==0 lanes (p==1 copy is dead)
    __syncthreads();

    const unsigned FULL = 0xffffffffu;

    auto step = [&](int t, const float (*hin)[HDIM], float (*hout)[HDIM]) {
        // --- both batches interleaved; h loaded in 4 chunks of 8 u64 each ---
        u64 aA0[GB], aB0[GB], aA1[GB], aB1[GB];
        #pragma unroll
        for (int g = 0; g < GB; g++) {
            const float xv = xs[g][t];
            aA0[g] = pack2(fmaf(xv, wih0, bia0), 0.0f);
            aB0[g] = 0ull;
            aA1[g] = pack2(fmaf(xv, wih1, bia1), 0.0f);
            aB1[g] = 0ull;
        }
        #pragma unroll
        for (int ch = 0; ch < 4; ch++) {
            u64 hc[GB][8];
            #pragma unroll
            for (int g = 0; g < GB; g++) {
                const ulonglong2* hp =
                    reinterpret_cast<const ulonglong2*>(hin[g]) + 4 * ch;
                #pragma unroll
                for (int k = 0; k < 4; k++) {
                    ulonglong2 v = hp[k];
                    hc[g][2 * k] = v.x; hc[g][2 * k + 1] = v.y;
                }
            }
            #pragma unroll
            for (int k = 0; k < 4; k++) {
                #pragma unroll
                for (int g = 0; g < GB; g++) {
                    aA0[g] = fma2(w0[8 * ch + k],     hc[g][k],     aA0[g]);
                    aB0[g] = fma2(w0[8 * ch + 4 + k], hc[g][4 + k], aB0[g]);
                    aA1[g] = fma2(w1[8 * ch + k],     hc[g][k],     aA1[g]);
                    aB1[g] = fma2(w1[8 * ch + 4 + k], hc[g][4 + k], aB1[g]);
                }
            }
        }
        // --- tails, both batches interleaved; tanh-only activations ---
        float t0[GB], t1[GB], s1[GB];
        #pragma unroll
        for (int g = 0; g < GB; g++) {
            t0[g] = tanhfa(lo_add_hi(add2(aA0[g], aB0[g])));  // p0: th(i/2)  p1: tanh(g)
            t1[g] = tanhfa(lo_add_hi(add2(aA1[g], aB1[g])));  // p0: th(f/2)  p1: th(o/2)
            s1[g] = fmaf(0.5f, t1[g], 0.5f);                  // p0: sig(f)   p1: sig(o)
        }
        // two INDEPENDENT shuffles: p0 receives tanh(g) and sig(o)
        float gr[GB], ox[GB];
        #pragma unroll
        for (int g = 0; g < GB; g++) {
            gr[g] = __shfl_xor_sync(FULL, t0[g], 1);
            ox[g] = __shfl_xor_sync(FULL, s1[g], 1);
        }
        #pragma unroll
        for (int g = 0; g < GB; g++) {
            const float gi = fmaf(0.5f, t0[g], 0.5f);    // p0: sig(i)
            // p0: c = sig(f)*c + sig(i)*tanh(g)   (p1 lanes: garbage, never read)
            c[g] = fmaf(s1[g], c[g], gi * gr[g]);
            const float tc = tanhfa(c[g]);
            if (p == 0) hout[g][m] = ox[g] * tc;         // h = sig(o)*tanh(c)
        }
    };

    #pragma unroll 1
    for (int t = 0; t < TLEN; t += 2) {
        step(t,     hsm[0], hsm[1]);
        __syncthreads();
        step(t + 1, hsm[1], hsm[0]);
        __syncthreads();
    }
    // t=1023 (odd) wrote hsm[0] -> final h in hsm[0]

    // ---- epilogue: out[b] = h_final . W_lin + b_lin ----
    const int w = tid >> 5, lane = tid & 31;
    if (w < GB) {
        const float* hf = hsm[0][w];
        float v = fmaf(hf[lane], W_lin[lane], hf[lane + 32] * W_lin[lane + 32]);
        #pragma unroll
        for (int d = 16; d >= 1; d >>= 1)
            v += __shfl_xor_sync(FULL, v, d);
        if (lane == 0) out[bb + w] = v + b_lin[0];
    }
}

extern "C" void kernel_launch(void* const* d_in, const int* in_sizes, int n_in,
                              void* d_out, int out_size) {
    const float* x     = (const float*)d_in[0];
    const float* W_ih  = (const float*)d_in[1];
    const float* W_hh  = (const float*)d_in[2];
    const float* b_ih  = (const float*)d_in[3];
    const float* b_hh  = (const float*)d_in[4];
    const float* W_lin = (const float*)d_in[5];
    const float* b_lin = (const float*)d_in[6];
    float* out = (float*)d_out;

    qlstm_kernel<<<NBLK, NTHR>>>(x, W_ih, W_hh, b_ih, b_hh, W_lin, b_lin, out);
}

// round 15
// speedup vs baseline: 1.9873x; 1.0005x over previous
#include <cuda_runtime.h>
#include <cuda_bf16.h>

// B=512, T=1024, IN=1, H=64
#define TLEN 1024
#define HDIM 64
#define GB   2              // batches per block (weights shared across both)
#define NTHR 128            // 64 units x 2 gate-pairs
#define NBLK 256            // 512 / GB -> 2 co-resident blocks per SM

typedef unsigned long long u64;

__device__ __forceinline__ u64 fma2(u64 a, u64 b, u64 c) {
    u64 d;
    asm("fma.rn.f32x2 %0, %1, %2, %3;" : "=l"(d) : "l"(a), "l"(b), "l"(c));
    return d;
}
__device__ __forceinline__ u64 add2(u64 a, u64 b) {
    u64 d;
    asm("add.rn.f32x2 %0, %1, %2;" : "=l"(d) : "l"(a), "l"(b));
    return d;
}
__device__ __forceinline__ u64 pack2(float lo, float hi) {
    u64 r;
    asm("mov.b64 %0, {%1, %2};" : "=l"(r) : "f"(lo), "f"(hi));
    return r;
}
__device__ __forceinline__ float lo_add_hi(u64 v) {
    float lo, hi;
    asm("mov.b64 {%0, %1}, %2;" : "=f"(lo), "=f"(hi) : "l"(v));
    return lo + hi;
}
// Single-MUFU tanh (sm_75+). Max abs err ~1.4e-5 -- far inside 1e-3 budget.
__device__ __forceinline__ float tanhfa(float x) {
    float r; asm("tanh.approx.f32 %0, %1;" : "=f"(r) : "f"(x)); return r;
}
// sigmoid(a) = 0.5*tanh(a/2) + 0.5 ; the /2 is PRE-FOLDED into the weight rows.

__global__ void __launch_bounds__(NTHR, 2) qlstm_kernel(
    const float* __restrict__ x,      // [512, 1024, 1]
    const float* __restrict__ W_ih,   // [256, 1]
    const float* __restrict__ W_hh,   // [256, 64]
    const float* __restrict__ b_ih,   // [256]
    const float* __restrict__ b_hh,   // [256]
    const float* __restrict__ W_lin,  // [1, 64]
    const float* __restrict__ b_lin,  // [1]
    float* __restrict__ out)          // [512]
{
    __shared__ __align__(16) float xs[GB][TLEN];       // 8 KB
    __shared__ __align__(16) float hsm[2][GB][HDIM];   // 1 KB, double-buffered

    const int tid = threadIdx.x;
    const int p   = tid & 1;      // 0 -> gates {i,f}; 1 -> gates {g,o}
    const int m   = tid >> 1;     // hidden unit 0..63
    const int bb  = blockIdx.x * GB;

    // ---- stage x (coalesced, one-time) ----
    for (int i = tid; i < GB * TLEN; i += NTHR)
        xs[i >> 10][i & (TLEN - 1)] = x[(bb + (i >> 10)) * TLEN + (i & (TLEN - 1))];

    // ---- 2 full-K W_hh rows -> regs (128 regs) ----
    // sigmoid rows prescaled by 0.5 (sigma(a) = 0.5*tanh(a/2)+0.5); g-row by 1.
    const int   r0   = p ? 128 + m : m;        // g-row  : i-row
    const int   r1   = p ? 192 + m : 64 + m;   // o-row  : f-row
    const float scl0 = p ? 1.0f : 0.5f;
    const float scl1 = 0.5f;

    u64 w0[32], w1[32];
    {
        const float4* a = reinterpret_cast<const float4*>(W_hh + r0 * HDIM);
        const float4* b = reinterpret_cast<const float4*>(W_hh + r1 * HDIM);
        #pragma unroll
        for (int k = 0; k < 16; k++) {
            float4 v = a[k];
            w0[2 * k]     = pack2(scl0 * v.x, scl0 * v.y);
            w0[2 * k + 1] = pack2(scl0 * v.z, scl0 * v.w);
            float4 u = b[k];
            w1[2 * k]     = pack2(scl1 * u.x, scl1 * u.y);
            w1[2 * k + 1] = pack2(scl1 * u.z, scl1 * u.w);
        }
    }
    const float wih0 = scl0 * W_ih[r0], bia0 = scl0 * (b_ih[r0] + b_hh[r0]);
    const float wih1 = scl1 * W_ih[r1], bia1 = scl1 * (b_ih[r1] + b_hh[r1]);

    for (int i = tid; i < 2 * GB * HDIM; i += NTHR)
        reinterpret_cast<float*>(hsm)[i] = 0.0f;

    float c[GB] = {0.0f, 0.0f};   // live in p==0 lanes (p==1 copy is dead)
    __syncthreads();

    // ---- anti-phase skew: odd blocks delay ~400 cyc so the two co-resident
    // blocks on each SM run tail-vs-FMA instead of tail-vs-tail. The offset
    // persists because each block's recurrence is self-timed. Data-dependent
    // chain (never-true store) so it cannot be optimized away. ----
    if (blockIdx.x & 1) {
        float d = xs[0][0];
        #pragma unroll
        for (int i = 0; i < 96; i++) d = fmaf(d, 1.0000001f, 1.0f);
        if (d == 12345.6789f) hsm[0][0][0] = d;   // never true for this chain
    }

    const unsigned FULL = 0xffffffffu;

    auto step = [&](int t, const float (*hin)[HDIM], float (*hout)[HDIM]) {
        // --- both batches interleaved; h loaded in 4 chunks of 8 u64 each ---
        u64 aA0[GB], aB0[GB], aA1[GB], aB1[GB];
        #pragma unroll
        for (int g = 0; g < GB; g++) {
            const float xv = xs[g][t];
            aA0[g] = pack2(fmaf(xv, wih0, bia0), 0.0f);
            aB0[g] = 0ull;
            aA1[g] = pack2(fmaf(xv, wih1, bia1), 0.0f);
            aB1[g] = 0ull;
        }
        #pragma unroll
        for (int ch = 0; ch < 4; ch++) {
            u64 hc[GB][8];
            #pragma unroll
            for (int g = 0; g < GB; g++) {
                const ulonglong2* hp =
                    reinterpret_cast<const ulonglong2*>(hin[g]) + 4 * ch;
                #pragma unroll
                for (int k = 0; k < 4; k++) {
                    ulonglong2 v = hp[k];
                    hc[g][2 * k] = v.x; hc[g][2 * k + 1] = v.y;
                }
            }
            #pragma unroll
            for (int k = 0; k < 4; k++) {
                #pragma unroll
                for (int g = 0; g < GB; g++) {
                    aA0[g] = fma2(w0[8 * ch + k],     hc[g][k],     aA0[g]);
                    aB0[g] = fma2(w0[8 * ch + 4 + k], hc[g][4 + k], aB0[g]);
                    aA1[g] = fma2(w1[8 * ch + k],     hc[g][k],     aA1[g]);
                    aB1[g] = fma2(w1[8 * ch + 4 + k], hc[g][4 + k], aB1[g]);
                }
            }
        }
        // --- tails, both batches interleaved; tanh-only activations ---
        float t0[GB], t1[GB], s1[GB];
        #pragma unroll
        for (int g = 0; g < GB; g++) {
            t0[g] = tanhfa(lo_add_hi(add2(aA0[g], aB0[g])));  // p0: th(i/2)  p1: tanh(g)
            t1[g] = tanhfa(lo_add_hi(add2(aA1[g], aB1[g])));  // p0: th(f/2)  p1: th(o/2)
            s1[g] = fmaf(0.5f, t1[g], 0.5f);                  // p0: sig(f)   p1: sig(o)
        }
        // two INDEPENDENT shuffles: p0 receives tanh(g) and sig(o)
        float gr[GB], ox[GB];
        #pragma unroll
        for (int g = 0; g < GB; g++) {
            gr[g] = __shfl_xor_sync(FULL, t0[g], 1);
            ox[g] = __shfl_xor_sync(FULL, s1[g], 1);
        }
        #pragma unroll
        for (int g = 0; g < GB; g++) {
            const float gi = fmaf(0.5f, t0[g], 0.5f);    // p0: sig(i)
            // p0: c = sig(f)*c + sig(i)*tanh(g)   (p1 lanes: garbage, never read)
            c[g] = fmaf(s1[g], c[g], gi * gr[g]);
            const float tc = tanhfa(c[g]);
            if (p == 0) hout[g][m] = ox[g] * tc;         // h = sig(o)*tanh(c)
        }
    };

    #pragma unroll 1
    for (int t = 0; t < TLEN; t += 2) {
        step(t,     hsm[0], hsm[1]);
        __syncthreads();
        step(t + 1, hsm[1], hsm[0]);
        __syncthreads();
    }
    // t=1023 (odd) wrote hsm[0] -> final h in hsm[0]

    // ---- epilogue: out[b] = h_final . W_lin + b_lin ----
    const int w = tid >> 5, lane = tid & 31;
    if (w < GB) {
        const float* hf = hsm[0][w];
        float v = fmaf(hf[lane], W_lin[lane], hf[lane + 32] * W_lin[lane + 32]);
        #pragma unroll
        for (int d = 16; d >= 1; d >>= 1)
            v += __shfl_xor_sync(FULL, v, d);
        if (lane == 0) out[bb + w] = v + b_lin[0];
    }
}

extern "C" void kernel_launch(void* const* d_in, const int* in_sizes, int n_in,
                              void* d_out, int out_size) {
    const float* x     = (const float*)d_in[0];
    const float* W_ih  = (const float*)d_in[1];
    const float* W_hh  = (const float*)d_in[2];
    const float* b_ih  = (const float*)d_in[3];
    const float* b_hh  = (const float*)d_in[4];
    const float* W_lin = (const float*)d_in[5];
    const float* b_lin = (const float*)d_in[6];
    float* out = (float*)d_out;

    qlstm_kernel<<<NBLK, NTHR>>>(x, W_ih, W_hh, b_ih, b_hh, W_lin, b_lin, out);
}